// round 11
// baseline (speedup 1.0000x reference)
#include <cuda_runtime.h>
#include <math.h>

#define BATCH 65536
#define NC 100
#define RT 16           // rows per tile in k1
#define XP 1005         // odd pitch: conflict-free gather banks
#define K1_THREADS 416  // 13 warps; 400 compute tasks
#define K1_BLOCKS 296   // persistent, 2 CTAs/SM target
#define N_TILES (BATCH / RT)   // 4096

// scratch: err transposed [cluster][row] so k2 reads coalesced
__device__ float g_errT[(size_t)NC * BATCH];

// ---------------- f32x2 helpers (k2) ----------------
__device__ __forceinline__ unsigned long long pk2(float lo, float hi) {
    unsigned long long r;
    asm("mov.b64 %0, {%1, %2};" : "=l"(r) : "f"(lo), "f"(hi));
    return r;
}
__device__ __forceinline__ void upk2(float& lo, float& hi, unsigned long long v) {
    asm("mov.b64 {%0, %1}, %2;" : "=f"(lo), "=f"(hi) : "l"(v));
}
__device__ __forceinline__ unsigned long long ffma2(unsigned long long a,
                                                    unsigned long long b,
                                                    unsigned long long c) {
    unsigned long long d;
    asm("fma.rn.f32x2 %0, %1, %2, %3;" : "=l"(d) : "l"(a), "l"(b), "l"(c));
    return d;
}

// ---------------------------------------------------------------------------
// Kernel 1: per-cluster autoencoders -> errT[c][row]. Persistent blocks,
// weights staged once. Per tile: stage 16 x-rows (scalar LDG/STS, odd pitch),
// sync, 400 tasks (c=tid>>2, q=tid&3, rows 4q..4q+3), sync.
// Weight LDS: 8 consecutive clusters/warp, 4-lane broadcast, 18c%32 distinct
// -> conflict-free. Gather LDS: q*20%32 distinct bank groups.
// ---------------------------------------------------------------------------
__global__ __launch_bounds__(K1_THREADS, 2) void k1_cluster(
    const float* __restrict__ x, const int* __restrict__ feat_idx,
    const float* __restrict__ W_enc, const float* __restrict__ b_enc,
    const float* __restrict__ W_dec, const float* __restrict__ b_dec)
{
    extern __shared__ float smem[];
    float* sx  = smem;                  // RT*XP = 16080 floats
    float* sWe = sx + RT * XP;          // 5000: [c][m][j]
    float* sbe = sWe + 5000;            // 500:  [c][j]
    float* sWd = sbe + 500;             // 5000: [c][j][m]
    float* sbd = sWd + 5000;            // 1000: [c][m]
    int*   sfid = (int*)(sbd + 1000);   // 1000: [c][m]

    const int tid = threadIdx.x;

    // one-time weight staging
    for (int i = tid; i < 5000; i += K1_THREADS) sWe[i] = W_enc[i];
    for (int i = tid; i < 500;  i += K1_THREADS) sbe[i] = b_enc[i];
    for (int i = tid; i < 5000; i += K1_THREADS) sWd[i] = W_dec[i];
    for (int i = tid; i < 1000; i += K1_THREADS) sbd[i] = b_dec[i];
    for (int i = tid; i < 1000; i += K1_THREADS) sfid[i] = feat_idx[i];

    const int c_task = tid >> 2;     // 0..99  (tid<400)
    const int q_task = tid & 3;      // 0..3 -> rows 4q..4q+3
    const bool active = (tid < 4 * NC);

    for (int t = blockIdx.x; t < N_TILES; t += K1_BLOCKS) {
        const float* xt = x + (size_t)t * RT * 1000;

        // stage 16 rows, scalar, coalesced; independent LDGs pipeline freely
        #pragma unroll
        for (int r = 0; r < RT; r++) {
            for (int col = tid; col < 1000; col += K1_THREADS)
                sx[r * XP + col] = xt[r * 1000 + col];
        }
        __syncthreads();

        if (active) {
            const int c = c_task;
            const float* xq = sx + q_task * 4 * XP;

            // ---- encoder (gather inline, xg not kept) ----
            float h[4][5];
            #pragma unroll
            for (int j = 0; j < 5; j++) {
                float b = sbe[c * 5 + j];
                #pragma unroll
                for (int r = 0; r < 4; r++) h[r][j] = b;
            }
            #pragma unroll
            for (int m = 0; m < 10; m++) {
                const int f = sfid[c * 10 + m];
                float xv[4];
                #pragma unroll
                for (int r = 0; r < 4; r++) xv[r] = xq[r * XP + f];
                #pragma unroll
                for (int j = 0; j < 5; j++) {
                    float w = sWe[c * 50 + m * 5 + j];
                    #pragma unroll
                    for (int r = 0; r < 4; r++) h[r][j] = fmaf(xv[r], w, h[r][j]);
                }
            }
            #pragma unroll
            for (int j = 0; j < 5; j++)
                #pragma unroll
                for (int r = 0; r < 4; r++) h[r][j] = fmaxf(h[r][j], 0.f);

            // ---- decoder + squared error (re-gather x) ----
            float acc[4] = {0.f, 0.f, 0.f, 0.f};
            #pragma unroll
            for (int m = 0; m < 10; m++) {
                float b = sbd[c * 10 + m];
                float rec[4];
                #pragma unroll
                for (int r = 0; r < 4; r++) rec[r] = b;
                #pragma unroll
                for (int j = 0; j < 5; j++) {
                    float w = sWd[c * 50 + j * 10 + m];
                    #pragma unroll
                    for (int r = 0; r < 4; r++) rec[r] = fmaf(h[r][j], w, rec[r]);
                }
                const int f = sfid[c * 10 + m];
                #pragma unroll
                for (int r = 0; r < 4; r++) {
                    float d = xq[r * XP + f] - rec[r];
                    acc[r] = fmaf(d, d, acc[r]);
                }
            }
            float4 o;
            o.x = sqrtf(acc[0] * 0.1f);
            o.y = sqrtf(acc[1] * 0.1f);
            o.z = sqrtf(acc[2] * 0.1f);
            o.w = sqrtf(acc[3] * 0.1f);
            *(float4*)&g_errT[(size_t)c * BATCH + t * RT + q_task * 4] = o;
        }
        __syncthreads();   // readers done before sx is re-staged
    }
}

// ---------------------------------------------------------------------------
// Kernel 2: meta autoencoder. 1 row/thread (grid 512), fma.rn.f32x2,
// 4-deep errT prefetch to cover L2 latency.
// ---------------------------------------------------------------------------
__global__ __launch_bounds__(128) void k2_meta(
    const float* __restrict__ We1, const float* __restrict__ be1,
    const float* __restrict__ Wd1, const float* __restrict__ bd1,
    float* __restrict__ out)
{
    __shared__ float sWe[NC * 50];   // [c*50 + j]  (natural: We1 is [c][j])
    __shared__ float sWd[NC * 50];   // [c*50 + j]  (transposed: Wd1 is [j][c])
    __shared__ float sbe[50];
    __shared__ float sbd[NC];

    const int tid = threadIdx.x;
    for (int i = tid; i < NC * 50; i += 128) sWe[i] = We1[i];
    for (int i = tid; i < NC * 50; i += 128) {
        int c = i / 50, j = i % 50;
        sWd[i] = Wd1[j * NC + c];
    }
    if (tid < 50) sbe[tid] = be1[tid];
    if (tid < NC) sbd[tid] = bd1[tid];
    __syncthreads();

    const int r = blockIdx.x * 128 + tid;
    const float* ep = g_errT + r;

    unsigned long long hm2[25];
    #pragma unroll
    for (int j = 0; j < 25; j++) hm2[j] = pk2(sbe[2 * j], sbe[2 * j + 1]);

    // ---- encoder with 4-deep prefetch ----
    float e[4];
    #pragma unroll
    for (int k = 0; k < 4; k++) e[k] = ep[(size_t)k * BATCH];

    #pragma unroll 1
    for (int c = 0; c < NC; c += 4) {
        float nx[4];
        #pragma unroll
        for (int k = 0; k < 4; k++) {
            int cn = c + 4 + k; if (cn > NC - 1) cn = NC - 1;
            nx[k] = ep[(size_t)cn * BATCH];
        }
        #pragma unroll
        for (int k = 0; k < 4; k++) {
            unsigned long long e2 = pk2(e[k], e[k]);
            const unsigned long long* w = (const unsigned long long*)(sWe + (c + k) * 50);
            #pragma unroll
            for (int j = 0; j < 25; j++) hm2[j] = ffma2(e2, w[j], hm2[j]);
        }
        #pragma unroll
        for (int k = 0; k < 4; k++) e[k] = nx[k];
    }
    #pragma unroll
    for (int j = 0; j < 25; j++) {
        float lo, hi;
        upk2(lo, hi, hm2[j]);
        hm2[j] = pk2(fmaxf(lo, 0.f), fmaxf(hi, 0.f));
    }

    // ---- decoder + squared error, same prefetch ----
    float acc = 0.f;
    #pragma unroll
    for (int k = 0; k < 4; k++) e[k] = ep[(size_t)k * BATCH];

    #pragma unroll 1
    for (int c = 0; c < NC; c += 4) {
        float nx[4];
        #pragma unroll
        for (int k = 0; k < 4; k++) {
            int cn = c + 4 + k; if (cn > NC - 1) cn = NC - 1;
            nx[k] = ep[(size_t)cn * BATCH];
        }
        #pragma unroll
        for (int k = 0; k < 4; k++) {
            const unsigned long long* w = (const unsigned long long*)(sWd + (c + k) * 50);
            unsigned long long rec2 = pk2(0.f, 0.f);
            #pragma unroll
            for (int j = 0; j < 25; j++) rec2 = ffma2(hm2[j], w[j], rec2);
            float lo, hi;
            upk2(lo, hi, rec2);
            float rec = lo + hi + sbd[c + k];
            float d = e[k] - rec;
            acc = fmaf(d, d, acc);
        }
        #pragma unroll
        for (int k = 0; k < 4; k++) e[k] = nx[k];
    }

    float f = sqrtf(acc * 0.01f);
    out[r] = 1.f / (1.f + __expf(-f));
}

extern "C" void kernel_launch(void* const* d_in, const int* in_sizes, int n_in,
                              void* d_out, int out_size)
{
    const float* x        = (const float*)d_in[0];
    const int*   feat_idx = (const int*)  d_in[1];
    const float* W_enc    = (const float*)d_in[2];
    const float* b_enc    = (const float*)d_in[3];
    const float* W_dec    = (const float*)d_in[4];
    const float* b_dec    = (const float*)d_in[5];
    const float* We1      = (const float*)d_in[6];
    const float* be1      = (const float*)d_in[7];
    const float* Wd1      = (const float*)d_in[8];
    const float* bd1      = (const float*)d_in[9];
    float* out = (float*)d_out;

    const int smem1 = (RT * XP + 5000 + 500 + 5000 + 1000 + 1000) * 4; // 114320 B
    cudaFuncSetAttribute(k1_cluster, cudaFuncAttributeMaxDynamicSharedMemorySize, smem1);

    k1_cluster<<<K1_BLOCKS, K1_THREADS, smem1>>>(x, feat_idx, W_enc, b_enc, W_dec, b_dec);
    k2_meta<<<BATCH / 128, 128>>>(We1, be1, Wd1, bd1, out);
}

// round 14
// speedup vs baseline: 2.8191x; 2.8191x over previous
#include <cuda_runtime.h>
#include <math.h>

#define BATCH 65536
#define NC 100
#define RT 8            // rows per tile (per buffer) in k1
#define XP 1004         // padded x pitch (16B-aligned rows for cp.async)
#define K1_THREADS 224
#define K1_BLOCKS 296   // 2 CTAs/SM * 148 SMs, persistent
#define N_TILES (BATCH / RT)   // 8192

typedef unsigned long long u64;

// scratch: err transposed [cluster][row] so k2 reads coalesced
__device__ float g_errT[(size_t)NC * BATCH];

// ---------------- f32x2 helpers ----------------
__device__ __forceinline__ u64 pk2(float lo, float hi) {
    u64 r;
    asm("mov.b64 %0, {%1, %2};" : "=l"(r) : "f"(lo), "f"(hi));
    return r;
}
__device__ __forceinline__ void upk2(float& lo, float& hi, u64 v) {
    asm("mov.b64 {%0, %1}, %2;" : "=f"(lo), "=f"(hi) : "l"(v));
}
__device__ __forceinline__ u64 ffma2(u64 a, u64 b, u64 c) {
    u64 d;
    asm("fma.rn.f32x2 %0, %1, %2, %3;" : "=l"(d) : "l"(a), "l"(b), "l"(c));
    return d;
}
__device__ __forceinline__ void cp_async16(float* smem_dst, const float4* gmem_src) {
    unsigned long long gp = (unsigned long long)gmem_src;
    unsigned sp;
    asm("{ .reg .u64 t; cvta.to.shared.u64 t, %1; cvt.u32.u64 %0, t; }"
        : "=r"(sp) : "l"(smem_dst));
    asm volatile("cp.async.cg.shared.global [%0], [%1], 16;" :: "r"(sp), "l"(gp));
}
__device__ __forceinline__ void cp_commit() {
    asm volatile("cp.async.commit_group;" ::: "memory");
}
__device__ __forceinline__ void cp_wait1() {
    asm volatile("cp.async.wait_group 1;" ::: "memory");
}

// ---------------------------------------------------------------------------
// Kernel 1: per-cluster autoencoders -> errT[c][row]. Persistent blocks,
// cp.async double-buffered x staging (R4 structure, proven), compute packed
// as f32x2 along the m-axis:
//   sWe transposed to [c][j][m] -> encoder weight LDS.64 m-pairs
//   sWd natural      [c][j][m] -> decoder weight LDS.64 m-pairs
//   xg packed once into m-pair f32x2, reused by encoder + error phases.
// Task: c=tid>>1, q=tid&1 (rows 4q..4q+3). Weight LDS 2-way broadcast,
// bank-pairs 25c+5j+m2 distinct over 16 consecutive c -> conflict-free.
// ---------------------------------------------------------------------------
__global__ __launch_bounds__(K1_THREADS, 2) void k1_cluster(
    const float* __restrict__ x, const int* __restrict__ feat_idx,
    const float* __restrict__ W_enc, const float* __restrict__ b_enc,
    const float* __restrict__ W_dec, const float* __restrict__ b_dec)
{
    extern __shared__ float smem[];
    float* sx  = smem;                  // 2 * RT * XP = 16064 floats
    float* sWe = sx + 2 * RT * XP;      // 5000: TRANSPOSED [c][j][m]
    float* sbe = sWe + 5000;            // 500:  [c][j]
    float* sWd = sbe + 500;             // 5000: natural [c][j][m]
    float* sbd = sWd + 5000;            // 1000: [c][m]
    int*   sfid = (int*)(sbd + 1000);   // 1000: [c][m]

    const int tid = threadIdx.x;

    // prologue: async-stage first tile into buffer 0
    {
        const int t0 = blockIdx.x;
        const float4* xsrc = (const float4*)(x + (size_t)t0 * RT * 1000);
        for (int i = tid; i < RT * 250; i += K1_THREADS) {
            int r = i / 250, c4 = i % 250;
            cp_async16(sx + r * XP + c4 * 4, xsrc + r * 250 + c4);
        }
        cp_commit();
    }

    // one-time weight staging; W_enc transposed [c][m][j] -> [c][j][m]
    for (int i = tid; i < 5000; i += K1_THREADS) {
        int c = i / 50, rr = i % 50, m = rr / 5, j = rr % 5;
        sWe[c * 50 + j * 10 + m] = W_enc[i];
    }
    for (int i = tid; i < 500;  i += K1_THREADS) sbe[i] = b_enc[i];
    for (int i = tid; i < 5000; i += K1_THREADS) sWd[i] = W_dec[i];
    for (int i = tid; i < 1000; i += K1_THREADS) sbd[i] = b_dec[i];
    for (int i = tid; i < 1000; i += K1_THREADS) sfid[i] = feat_idx[i];

    const int c_task = tid >> 1;
    const int q_task = tid & 1;
    const u64 NEG1 = pk2(-1.f, -1.f);

    int buf = 0;
    for (int t = blockIdx.x; t < N_TILES; t += K1_BLOCKS) {
        // stage NEXT tile into the other buffer
        const int tn = t + K1_BLOCKS;
        if (tn < N_TILES) {
            const float4* xsrc = (const float4*)(x + (size_t)tn * RT * 1000);
            float* dst = sx + (buf ^ 1) * RT * XP;
            for (int i = tid; i < RT * 250; i += K1_THREADS) {
                int r = i / 250, c4 = i % 250;
                cp_async16(dst + r * XP + c4 * 4, xsrc + r * 250 + c4);
            }
        }
        cp_commit();
        cp_wait1();          // tile t's data has landed
        __syncthreads();

        if (tid < 2 * NC) {
            const int c = c_task;
            const float* xq = sx + buf * RT * XP + q_task * 4 * XP;
            const int cf = c * 10;

            // gather + pack m-pairs: xg2[r][m2] = (x[2m2], x[2m2+1])
            u64 xg2[4][5];
            #pragma unroll
            for (int m2 = 0; m2 < 5; m2++) {
                const int f0 = sfid[cf + 2 * m2];
                const int f1 = sfid[cf + 2 * m2 + 1];
                #pragma unroll
                for (int r = 0; r < 4; r++)
                    xg2[r][m2] = pk2(xq[r * XP + f0], xq[r * XP + f1]);
            }

            // ---- encoder: h2 accumulates (even-m, odd-m) partial sums ----
            u64 h2[4][5];
            #pragma unroll
            for (int r = 0; r < 4; r++)
                #pragma unroll
                for (int j = 0; j < 5; j++) h2[r][j] = 0ull;

            #pragma unroll
            for (int j = 0; j < 5; j++)
                #pragma unroll
                for (int m2 = 0; m2 < 5; m2++) {
                    u64 w2 = *(const u64*)&sWe[c * 50 + j * 10 + 2 * m2];
                    #pragma unroll
                    for (int r = 0; r < 4; r++)
                        h2[r][j] = ffma2(xg2[r][m2], w2, h2[r][j]);
                }

            float h[4][5];
            #pragma unroll
            for (int j = 0; j < 5; j++) {
                float b = sbe[c * 5 + j];
                #pragma unroll
                for (int r = 0; r < 4; r++) {
                    float lo, hi;
                    upk2(lo, hi, h2[r][j]);
                    h[r][j] = fmaxf(lo + hi + b, 0.f);
                }
            }

            // ---- decoder: rec2[r][m2] over m-pairs ----
            u64 rec2[4][5];
            #pragma unroll
            for (int m2 = 0; m2 < 5; m2++) {
                u64 b2 = *(const u64*)&sbd[c * 10 + 2 * m2];
                #pragma unroll
                for (int r = 0; r < 4; r++) rec2[r][m2] = b2;
            }
            #pragma unroll
            for (int j = 0; j < 5; j++) {
                u64 hb[4];
                #pragma unroll
                for (int r = 0; r < 4; r++) hb[r] = pk2(h[r][j], h[r][j]);
                #pragma unroll
                for (int m2 = 0; m2 < 5; m2++) {
                    u64 w2 = *(const u64*)&sWd[c * 50 + j * 10 + 2 * m2];
                    #pragma unroll
                    for (int r = 0; r < 4; r++)
                        rec2[r][m2] = ffma2(hb[r], w2, rec2[r][m2]);
                }
            }

            // ---- squared error (packed) ----
            u64 acc2[4] = {0ull, 0ull, 0ull, 0ull};
            #pragma unroll
            for (int m2 = 0; m2 < 5; m2++)
                #pragma unroll
                for (int r = 0; r < 4; r++) {
                    u64 d2 = ffma2(rec2[r][m2], NEG1, xg2[r][m2]);
                    acc2[r] = ffma2(d2, d2, acc2[r]);
                }

            float4 o;
            float lo, hi;
            upk2(lo, hi, acc2[0]); o.x = sqrtf((lo + hi) * 0.1f);
            upk2(lo, hi, acc2[1]); o.y = sqrtf((lo + hi) * 0.1f);
            upk2(lo, hi, acc2[2]); o.z = sqrtf((lo + hi) * 0.1f);
            upk2(lo, hi, acc2[3]); o.w = sqrtf((lo + hi) * 0.1f);
            *(float4*)&g_errT[(size_t)c * BATCH + t * RT + q_task * 4] = o;
        }
        __syncthreads();     // all readers of buf done before it is re-staged
        buf ^= 1;
    }
}

// ---------------------------------------------------------------------------
// Kernel 2: meta autoencoder. 1 row/thread (grid 512), fma.rn.f32x2,
// 4-deep errT prefetch to cover L2 latency.  (R8 verbatim, 60.2 us proven)
// ---------------------------------------------------------------------------
__global__ __launch_bounds__(128) void k2_meta(
    const float* __restrict__ We1, const float* __restrict__ be1,
    const float* __restrict__ Wd1, const float* __restrict__ bd1,
    float* __restrict__ out)
{
    __shared__ float sWe[NC * 50];   // [c*50 + j]
    __shared__ float sWd[NC * 50];   // [c*50 + j]  (transposed from [j][c])
    __shared__ float sbe[50];
    __shared__ float sbd[NC];

    const int tid = threadIdx.x;
    for (int i = tid; i < NC * 50; i += 128) sWe[i] = We1[i];
    for (int i = tid; i < NC * 50; i += 128) {
        int c = i / 50, j = i % 50;
        sWd[i] = Wd1[j * NC + c];
    }
    if (tid < 50) sbe[tid] = be1[tid];
    if (tid < NC) sbd[tid] = bd1[tid];
    __syncthreads();

    const int r = blockIdx.x * 128 + tid;
    const float* ep = g_errT + r;

    u64 hm2[25];
    #pragma unroll
    for (int j = 0; j < 25; j++) hm2[j] = pk2(sbe[2 * j], sbe[2 * j + 1]);

    float e[4];
    #pragma unroll
    for (int k = 0; k < 4; k++) e[k] = ep[(size_t)k * BATCH];

    #pragma unroll 1
    for (int c = 0; c < NC; c += 4) {
        float nx[4];
        #pragma unroll
        for (int k = 0; k < 4; k++) {
            int cn = c + 4 + k; if (cn > NC - 1) cn = NC - 1;
            nx[k] = ep[(size_t)cn * BATCH];
        }
        #pragma unroll
        for (int k = 0; k < 4; k++) {
            u64 e2 = pk2(e[k], e[k]);
            const u64* w = (const u64*)(sWe + (c + k) * 50);
            #pragma unroll
            for (int j = 0; j < 25; j++) hm2[j] = ffma2(e2, w[j], hm2[j]);
        }
        #pragma unroll
        for (int k = 0; k < 4; k++) e[k] = nx[k];
    }
    #pragma unroll
    for (int j = 0; j < 25; j++) {
        float lo, hi;
        upk2(lo, hi, hm2[j]);
        hm2[j] = pk2(fmaxf(lo, 0.f), fmaxf(hi, 0.f));
    }

    float acc = 0.f;
    #pragma unroll
    for (int k = 0; k < 4; k++) e[k] = ep[(size_t)k * BATCH];

    #pragma unroll 1
    for (int c = 0; c < NC; c += 4) {
        float nx[4];
        #pragma unroll
        for (int k = 0; k < 4; k++) {
            int cn = c + 4 + k; if (cn > NC - 1) cn = NC - 1;
            nx[k] = ep[(size_t)cn * BATCH];
        }
        #pragma unroll
        for (int k = 0; k < 4; k++) {
            const u64* w = (const u64*)(sWd + (c + k) * 50);
            u64 rec2 = 0ull;
            #pragma unroll
            for (int j = 0; j < 25; j++) rec2 = ffma2(hm2[j], w[j], rec2);
            float lo, hi;
            upk2(lo, hi, rec2);
            float rec = lo + hi + sbd[c + k];
            float d = e[k] - rec;
            acc = fmaf(d, d, acc);
        }
        #pragma unroll
        for (int k = 0; k < 4; k++) e[k] = nx[k];
    }

    float f = sqrtf(acc * 0.01f);
    out[r] = 1.f / (1.f + __expf(-f));
}

extern "C" void kernel_launch(void* const* d_in, const int* in_sizes, int n_in,
                              void* d_out, int out_size)
{
    const float* x        = (const float*)d_in[0];
    const int*   feat_idx = (const int*)  d_in[1];
    const float* W_enc    = (const float*)d_in[2];
    const float* b_enc    = (const float*)d_in[3];
    const float* W_dec    = (const float*)d_in[4];
    const float* b_dec    = (const float*)d_in[5];
    const float* We1      = (const float*)d_in[6];
    const float* be1      = (const float*)d_in[7];
    const float* Wd1      = (const float*)d_in[8];
    const float* bd1      = (const float*)d_in[9];
    float* out = (float*)d_out;

    const int smem1 = (2 * RT * XP + 5000 + 500 + 5000 + 1000 + 1000) * 4; // 114256 B
    cudaFuncSetAttribute(k1_cluster, cudaFuncAttributeMaxDynamicSharedMemorySize, smem1);

    k1_cluster<<<K1_BLOCKS, K1_THREADS, smem1>>>(x, feat_idx, W_enc, b_enc, W_dec, b_dec);
    k2_meta<<<BATCH / 128, 128>>>(We1, be1, Wd1, bd1, out);
}

// round 17
// speedup vs baseline: 2.8905x; 1.0253x over previous
#include <cuda_runtime.h>
#include <math.h>

#define BATCH 65536
#define NC 100
#define RT 8            // rows per tile (per buffer) in k1
#define XP 1004         // padded x pitch (16B-aligned rows for cp.async)
#define K1_THREADS 448
#define K1_BLOCKS 296   // 2 CTAs/SM * 148 SMs, persistent
#define N_TILES (BATCH / RT)   // 8192
#define WP 52           // k2 weight row pitch (16B-aligned rows)

typedef unsigned long long u64;

// scratch: err transposed [cluster][row] so k2 reads coalesced
__device__ float g_errT[(size_t)NC * BATCH];

// ---------------- f32x2 helpers ----------------
__device__ __forceinline__ u64 pk2(float lo, float hi) {
    u64 r;
    asm("mov.b64 %0, {%1, %2};" : "=l"(r) : "f"(lo), "f"(hi));
    return r;
}
__device__ __forceinline__ void upk2(float& lo, float& hi, u64 v) {
    asm("mov.b64 {%0, %1}, %2;" : "=f"(lo), "=f"(hi) : "l"(v));
}
__device__ __forceinline__ u64 ffma2(u64 a, u64 b, u64 c) {
    u64 d;
    asm("fma.rn.f32x2 %0, %1, %2, %3;" : "=l"(d) : "l"(a), "l"(b), "l"(c));
    return d;
}
__device__ __forceinline__ void cp_async16(float* smem_dst, const float4* gmem_src) {
    unsigned long long gp = (unsigned long long)gmem_src;
    unsigned sp;
    asm("{ .reg .u64 t; cvta.to.shared.u64 t, %1; cvt.u32.u64 %0, t; }"
        : "=r"(sp) : "l"(smem_dst));
    asm volatile("cp.async.cg.shared.global [%0], [%1], 16;" :: "r"(sp), "l"(gp));
}
__device__ __forceinline__ void cp_commit() {
    asm volatile("cp.async.commit_group;" ::: "memory");
}
__device__ __forceinline__ void cp_wait1() {
    asm volatile("cp.async.wait_group 1;" ::: "memory");
}

// ---------------------------------------------------------------------------
// Kernel 1: per-cluster autoencoders -> errT[c][row]. Persistent blocks,
// cp.async double-buffered x staging, f32x2 compute along m-axis.
// 448 threads, 2 rows/thread: c = tid>>2, h = tid&3 (rows 2h, 2h+1).
// 28 warps/SM (2 CTAs x 14) for latency hiding; ~70 regs/thread.
// ---------------------------------------------------------------------------
__global__ __launch_bounds__(K1_THREADS, 2) void k1_cluster(
    const float* __restrict__ x, const int* __restrict__ feat_idx,
    const float* __restrict__ W_enc, const float* __restrict__ b_enc,
    const float* __restrict__ W_dec, const float* __restrict__ b_dec)
{
    extern __shared__ float smem[];
    float* sx  = smem;                  // 2 * RT * XP = 16064 floats
    float* sWe = sx + 2 * RT * XP;      // 5000: TRANSPOSED [c][j][m]
    float* sbe = sWe + 5000;            // 500:  [c][j]
    float* sWd = sbe + 500;             // 5000: natural [c][j][m]
    float* sbd = sWd + 5000;            // 1000: [c][m]
    int*   sfid = (int*)(sbd + 1000);   // 1000: [c][m]

    const int tid = threadIdx.x;

    // prologue: async-stage first tile into buffer 0
    {
        const int t0 = blockIdx.x;
        const float4* xsrc = (const float4*)(x + (size_t)t0 * RT * 1000);
        for (int i = tid; i < RT * 250; i += K1_THREADS) {
            int r = i / 250, c4 = i % 250;
            cp_async16(sx + r * XP + c4 * 4, xsrc + r * 250 + c4);
        }
        cp_commit();
    }

    // one-time weight staging; W_enc transposed [c][m][j] -> [c][j][m]
    for (int i = tid; i < 5000; i += K1_THREADS) {
        int c = i / 50, rr = i % 50, m = rr / 5, j = rr % 5;
        sWe[c * 50 + j * 10 + m] = W_enc[i];
    }
    for (int i = tid; i < 500;  i += K1_THREADS) sbe[i] = b_enc[i];
    for (int i = tid; i < 5000; i += K1_THREADS) sWd[i] = W_dec[i];
    for (int i = tid; i < 1000; i += K1_THREADS) sbd[i] = b_dec[i];
    for (int i = tid; i < 1000; i += K1_THREADS) sfid[i] = feat_idx[i];

    const int c_task = tid >> 2;     // 0..99 for tid<400
    const int h_task = tid & 3;      // rows 2h, 2h+1
    const u64 NEG1 = pk2(-1.f, -1.f);

    int buf = 0;
    for (int t = blockIdx.x; t < N_TILES; t += K1_BLOCKS) {
        // stage NEXT tile into the other buffer
        const int tn = t + K1_BLOCKS;
        if (tn < N_TILES) {
            const float4* xsrc = (const float4*)(x + (size_t)tn * RT * 1000);
            float* dst = sx + (buf ^ 1) * RT * XP;
            for (int i = tid; i < RT * 250; i += K1_THREADS) {
                int r = i / 250, c4 = i % 250;
                cp_async16(dst + r * XP + c4 * 4, xsrc + r * 250 + c4);
            }
        }
        cp_commit();
        cp_wait1();          // tile t's data has landed
        __syncthreads();

        if (tid < 4 * NC) {
            const int c = c_task;
            const float* xq = sx + buf * RT * XP + h_task * 2 * XP;
            const int cf = c * 10;

            // gather + pack m-pairs: xg2[r][m2] = (x[2m2], x[2m2+1])
            u64 xg2[2][5];
            #pragma unroll
            for (int m2 = 0; m2 < 5; m2++) {
                const int f0 = sfid[cf + 2 * m2];
                const int f1 = sfid[cf + 2 * m2 + 1];
                #pragma unroll
                for (int r = 0; r < 2; r++)
                    xg2[r][m2] = pk2(xq[r * XP + f0], xq[r * XP + f1]);
            }

            // ---- encoder ----
            u64 h2[2][5];
            #pragma unroll
            for (int r = 0; r < 2; r++)
                #pragma unroll
                for (int j = 0; j < 5; j++) h2[r][j] = 0ull;

            #pragma unroll
            for (int j = 0; j < 5; j++)
                #pragma unroll
                for (int m2 = 0; m2 < 5; m2++) {
                    u64 w2 = *(const u64*)&sWe[c * 50 + j * 10 + 2 * m2];
                    #pragma unroll
                    for (int r = 0; r < 2; r++)
                        h2[r][j] = ffma2(xg2[r][m2], w2, h2[r][j]);
                }

            float h[2][5];
            #pragma unroll
            for (int j = 0; j < 5; j++) {
                float b = sbe[c * 5 + j];
                #pragma unroll
                for (int r = 0; r < 2; r++) {
                    float lo, hi;
                    upk2(lo, hi, h2[r][j]);
                    h[r][j] = fmaxf(lo + hi + b, 0.f);
                }
            }

            // ---- decoder ----
            u64 rec2[2][5];
            #pragma unroll
            for (int m2 = 0; m2 < 5; m2++) {
                u64 b2 = *(const u64*)&sbd[c * 10 + 2 * m2];
                #pragma unroll
                for (int r = 0; r < 2; r++) rec2[r][m2] = b2;
            }
            #pragma unroll
            for (int j = 0; j < 5; j++) {
                u64 hb[2];
                #pragma unroll
                for (int r = 0; r < 2; r++) hb[r] = pk2(h[r][j], h[r][j]);
                #pragma unroll
                for (int m2 = 0; m2 < 5; m2++) {
                    u64 w2 = *(const u64*)&sWd[c * 50 + j * 10 + 2 * m2];
                    #pragma unroll
                    for (int r = 0; r < 2; r++)
                        rec2[r][m2] = ffma2(hb[r], w2, rec2[r][m2]);
                }
            }

            // ---- squared error ----
            u64 acc2[2] = {0ull, 0ull};
            #pragma unroll
            for (int m2 = 0; m2 < 5; m2++)
                #pragma unroll
                for (int r = 0; r < 2; r++) {
                    u64 d2 = ffma2(rec2[r][m2], NEG1, xg2[r][m2]);
                    acc2[r] = ffma2(d2, d2, acc2[r]);
                }

            float2 o;
            float lo, hi;
            upk2(lo, hi, acc2[0]); o.x = sqrtf((lo + hi) * 0.1f);
            upk2(lo, hi, acc2[1]); o.y = sqrtf((lo + hi) * 0.1f);
            *(float2*)&g_errT[(size_t)c * BATCH + t * RT + h_task * 2] = o;
        }
        __syncthreads();     // all readers of buf done before it is re-staged
        buf ^= 1;
    }
}

// ---------------------------------------------------------------------------
// Kernel 2: meta autoencoder. 1 row/thread (grid 512), f32x2, 4-deep errT
// prefetch; weight rows padded to 52 floats so loads are LDS.128.
// ---------------------------------------------------------------------------
__global__ __launch_bounds__(128) void k2_meta(
    const float* __restrict__ We1, const float* __restrict__ be1,
    const float* __restrict__ Wd1, const float* __restrict__ bd1,
    float* __restrict__ out)
{
    __shared__ __align__(16) float sWe[NC * WP];   // [c*WP + j]
    __shared__ __align__(16) float sWd[NC * WP];   // [c*WP + j] (transposed from [j][c])
    __shared__ float sbe[50];
    __shared__ float sbd[NC];

    const int tid = threadIdx.x;
    for (int i = tid; i < NC * 50; i += 128) {
        int c = i / 50, j = i % 50;
        sWe[c * WP + j] = We1[i];
        sWd[c * WP + j] = Wd1[j * NC + c];
    }
    if (tid < 50) sbe[tid] = be1[tid];
    if (tid < NC) sbd[tid] = bd1[tid];
    __syncthreads();

    const int r = blockIdx.x * 128 + tid;
    const float* ep = g_errT + r;

    u64 hm2[25];
    #pragma unroll
    for (int j = 0; j < 25; j++) hm2[j] = pk2(sbe[2 * j], sbe[2 * j + 1]);

    // ---- encoder with 4-deep prefetch; weights via LDS.128 ----
    float e[4];
    #pragma unroll
    for (int k = 0; k < 4; k++) e[k] = ep[(size_t)k * BATCH];

    #pragma unroll 1
    for (int c = 0; c < NC; c += 4) {
        float nx[4];
        #pragma unroll
        for (int k = 0; k < 4; k++) {
            int cn = c + 4 + k; if (cn > NC - 1) cn = NC - 1;
            nx[k] = ep[(size_t)cn * BATCH];
        }
        #pragma unroll
        for (int k = 0; k < 4; k++) {
            u64 e2 = pk2(e[k], e[k]);
            const float4* w4 = (const float4*)(sWe + (c + k) * WP);
            #pragma unroll
            for (int v = 0; v < 12; v++) {
                float4 w = w4[v];
                hm2[2 * v]     = ffma2(e2, pk2(w.x, w.y), hm2[2 * v]);
                hm2[2 * v + 1] = ffma2(e2, pk2(w.z, w.w), hm2[2 * v + 1]);
            }
            u64 wt = *(const u64*)(sWe + (c + k) * WP + 48);
            hm2[24] = ffma2(e2, wt, hm2[24]);
        }
        #pragma unroll
        for (int k = 0; k < 4; k++) e[k] = nx[k];
    }
    #pragma unroll
    for (int j = 0; j < 25; j++) {
        float lo, hi;
        upk2(lo, hi, hm2[j]);
        hm2[j] = pk2(fmaxf(lo, 0.f), fmaxf(hi, 0.f));
    }

    // ---- decoder + squared error, same pattern ----
    float acc = 0.f;
    #pragma unroll
    for (int k = 0; k < 4; k++) e[k] = ep[(size_t)k * BATCH];

    #pragma unroll 1
    for (int c = 0; c < NC; c += 4) {
        float nx[4];
        #pragma unroll
        for (int k = 0; k < 4; k++) {
            int cn = c + 4 + k; if (cn > NC - 1) cn = NC - 1;
            nx[k] = ep[(size_t)cn * BATCH];
        }
        #pragma unroll
        for (int k = 0; k < 4; k++) {
            const float4* w4 = (const float4*)(sWd + (c + k) * WP);
            u64 rec2 = 0ull;
            #pragma unroll
            for (int v = 0; v < 12; v++) {
                float4 w = w4[v];
                rec2 = ffma2(hm2[2 * v], pk2(w.x, w.y), rec2);
                rec2 = ffma2(hm2[2 * v + 1], pk2(w.z, w.w), rec2);
            }
            u64 wt = *(const u64*)(sWd + (c + k) * WP + 48);
            rec2 = ffma2(hm2[24], wt, rec2);
            float lo, hi;
            upk2(lo, hi, rec2);
            float rec = lo + hi + sbd[c + k];
            float d = e[k] - rec;
            acc = fmaf(d, d, acc);
        }
        #pragma unroll
        for (int k = 0; k < 4; k++) e[k] = nx[k];
    }

    float f = sqrtf(acc * 0.01f);
    out[r] = 1.f / (1.f + __expf(-f));
}

extern "C" void kernel_launch(void* const* d_in, const int* in_sizes, int n_in,
                              void* d_out, int out_size)
{
    const float* x        = (const float*)d_in[0];
    const int*   feat_idx = (const int*)  d_in[1];
    const float* W_enc    = (const float*)d_in[2];
    const float* b_enc    = (const float*)d_in[3];
    const float* W_dec    = (const float*)d_in[4];
    const float* b_dec    = (const float*)d_in[5];
    const float* We1      = (const float*)d_in[6];
    const float* be1      = (const float*)d_in[7];
    const float* Wd1      = (const float*)d_in[8];
    const float* bd1      = (const float*)d_in[9];
    float* out = (float*)d_out;

    const int smem1 = (2 * RT * XP + 5000 + 500 + 5000 + 1000 + 1000) * 4; // 114256 B
    cudaFuncSetAttribute(k1_cluster, cudaFuncAttributeMaxDynamicSharedMemorySize, smem1);

    k1_cluster<<<K1_BLOCKS, K1_THREADS, smem1>>>(x, feat_idx, W_enc, b_enc, W_dec, b_dec);
    k2_meta<<<BATCH / 128, 128>>>(We1, be1, Wd1, bd1, out);
}